// round 4
// baseline (speedup 1.0000x reference)
#include <cuda_runtime.h>
#include <cuda_fp16.h>
#include <cstdint>
#include <math.h>

#define MM 16384          // B*L
#define KW 16             // window

__device__ __half g_xhi[(size_t)MM * 256];
__device__ __half g_xlo[(size_t)MM * 256];
__device__ __half g_Hhi[2][(size_t)MM * 256];
__device__ __half g_Hlo[2][(size_t)MM * 256];
__device__ float  g_Gx[(size_t)MM * 768];          // x@W_ih^T + b_ih, gate-major per ct
__device__ __half g_Wih_p[8 * 4 * 96 * 64];        // [ct][kc][row96][k64]
__device__ __half g_Whh_p[8 * 4 * 96 * 64];

#define SWZ(o) ((o) ^ (((o) >> 3) & 0x70))

#define OFF_B 0
#define OFF_A 49152
#define SMEM_BYTES 114688

__device__ __forceinline__ uint32_t smem_u32(const void* p) {
    uint32_t a;
    asm("{ .reg .u64 t; cvta.to.shared.u64 t, %1; cvt.u32.u64 %0, t; }"
        : "=r"(a) : "l"(p));
    return a;
}
__device__ __forceinline__ void cp16(uint32_t d, const void* s) {
    asm volatile("cp.async.cg.shared.global [%0], [%1], 16;"
                 :: "r"(d), "l"(s) : "memory");
}
__device__ __forceinline__ void cp_commit() { asm volatile("cp.async.commit_group;" ::: "memory"); }
__device__ __forceinline__ void cp_wait1()  { asm volatile("cp.async.wait_group 1;" ::: "memory"); }
__device__ __forceinline__ void cp_wait0()  { asm volatile("cp.async.wait_group 0;" ::: "memory"); }

__device__ __forceinline__ void ldm4(uint32_t a, uint32_t* r) {
    asm volatile("ldmatrix.sync.aligned.m8n8.x4.shared.b16 {%0,%1,%2,%3}, [%4];"
                 : "=r"(r[0]), "=r"(r[1]), "=r"(r[2]), "=r"(r[3]) : "r"(a));
}
__device__ __forceinline__ void mma16816(float* c, const uint32_t* a, const uint32_t* b) {
    asm volatile("mma.sync.aligned.m16n8k16.row.col.f32.f16.f16.f32 "
                 "{%0,%1,%2,%3}, {%4,%5,%6,%7}, {%8,%9}, {%0,%1,%2,%3};"
                 : "+f"(c[0]), "+f"(c[1]), "+f"(c[2]), "+f"(c[3])
                 : "r"(a[0]), "r"(a[1]), "r"(a[2]), "r"(a[3]), "r"(b[0]), "r"(b[1]));
}

__global__ void pack_x_kernel(const float* __restrict__ x) {
    size_t i = (size_t)blockIdx.x * 256 + threadIdx.x;
    float f = x[i];
    __half h = __float2half(f);
    g_xhi[i] = h;
    g_xlo[i] = __float2half(f - __half2float(h));
}

__global__ void pack_w_kernel(const float* __restrict__ W_ih,
                              const float* __restrict__ W_hh) {
    int idx = blockIdx.x * 256 + threadIdx.x;        // < 196608
    int k   = idx & 63;
    int r2  = idx >> 6;
    int row = r2 % 96;
    int r3  = r2 / 96;
    int kc  = r3 & 3;
    int ct  = r3 >> 2;
    int g = row >> 5, c = row & 31;
    int widx = (g * 256 + ct * 32 + c) * 256 + kc * 64 + k;
    g_Wih_p[idx] = __float2half(W_ih[widx]);
    g_Whh_p[idx] = __float2half(W_hh[widx]);
}

__global__ void step0_kernel(const float* __restrict__ b_ih,
                             const float* __restrict__ b_hh) {
    int idx = blockIdx.x * 256 + threadIdx.x;
    int m = idx >> 8, col = idx & 255;
    int ct = col >> 5, c = col & 31;
    int l = m & 1023;
    float gir, giz, gin;
    if (l - (KW - 1) >= 0) {
        const float* gx = &g_Gx[(size_t)(m - (KW - 1)) * 768 + ct * 96];
        gir = gx[c]; giz = gx[32 + c]; gin = gx[64 + c];
    } else {
        gir = b_ih[col];
        giz = b_ih[256 + col];
        gin = b_ih[512 + col];
    }
    float r = 1.f / (1.f + __expf(-(gir + b_hh[col])));
    float z = 1.f / (1.f + __expf(-(giz + b_hh[256 + col])));
    float n = tanhf(fmaf(r, b_hh[512 + col], gin));
    float h = (1.f - z) * n;
    __half hh = __float2half(h);
    g_Hhi[0][idx] = hh;
    g_Hlo[0][idx] = __float2half(h - __half2float(hh));
}

__global__ void __launch_bounds__(256, 2)
gemm_fused(int mode, int t, int src, int dst,
           const float* __restrict__ b_ih, const float* __restrict__ b_hh,
           float* __restrict__ fout)
{
    extern __shared__ char smem[];
    const int tid = threadIdx.x, wid = tid >> 5, lane = tid & 31;
    const int ct = blockIdx.x;
    const int m0 = blockIdx.y * 128;
    const uint32_t sb = smem_u32(smem);

    const __half* __restrict__ Ahi = (mode == 0) ? g_xhi : g_Hhi[src];
    const __half* __restrict__ Alo = (mode == 0) ? g_xlo : g_Hlo[src];
    const __half* __restrict__ B   = (mode == 0) ? g_Wih_p : g_Whh_p;
    const bool lo_all = (mode == 0);

    float acc[12][4];
    #pragma unroll
    for (int i = 0; i < 12; i++)
        #pragma unroll
        for (int j = 0; j < 4; j++) acc[i][j] = 0.f;

    // B: all 4 k-chunks once (48KB), part of cp.async group 0
    {
        const __half* Bbase = B + (size_t)ct * 4 * 96 * 64;
        #pragma unroll
        for (int r = 0; r < 12; r++) {
            int idx = tid + 256 * r;             // < 3072
            int kc = idx / 768;
            int e  = idx - kc * 768;
            int row = e >> 3, u = e & 7;
            cp16(sb + OFF_B + kc * 12288 + SWZ(row * 128 + u * 16),
                 Bbase + (size_t)(kc * 96 + row) * 64 + u * 8);
        }
    }

    auto load_A = [&](int kc, int buf) {
        uint32_t base = sb + OFF_A + buf * 32768;
        #pragma unroll
        for (int r = 0; r < 4; r++) {
            int idx = tid + 256 * r;             // < 1024
            int row = idx >> 3, u = idx & 7;
            size_t off = (size_t)(m0 + row) * 256 + kc * 64 + u * 8;
            uint32_t d = SWZ(row * 128 + u * 16);
            cp16(base + d, Ahi + off);
            cp16(base + 16384 + d, Alo + off);
        }
        cp_commit();
    };

    load_A(0, 0);       // group 0 = B + A0
    load_A(1, 1);       // group 1 = A1

    #pragma unroll 1
    for (int kc = 0; kc < 4; kc++) {
        if (kc < 2) cp_wait1(); else cp_wait0();
        __syncthreads();

        uint32_t abufh = sb + OFF_A + (kc & 1) * 32768;
        uint32_t abufl = abufh + 16384;
        uint32_t bbuf  = sb + OFF_B + kc * 12288;

        #pragma unroll
        for (int ks = 0; ks < 4; ks++) {
            uint32_t af[4], al[4];
            {
                int row = wid * 16 + (lane & 15);
                int colb = ks * 32 + ((lane >> 4) << 4);
                uint32_t d = SWZ(row * 128 + colb);
                ldm4(abufh + d, af);
                ldm4(abufl + d, al);
            }
            #pragma unroll
            for (int p = 0; p < 6; p++) {
                uint32_t bf[4];
                int n = p * 16 + (lane & 7) + ((lane >> 4) << 3);
                int colb = ks * 32 + (((lane >> 3) & 1) << 4);
                ldm4(bbuf + SWZ(n * 128 + colb), bf);
                mma16816(acc[p * 2 + 0], af, bf + 0);
                mma16816(acc[p * 2 + 1], af, bf + 2);
                if (lo_all || p >= 4) {
                    mma16816(acc[p * 2 + 0], al, bf + 0);
                    mma16816(acc[p * 2 + 1], al, bf + 2);
                }
            }
        }
        __syncthreads();
        if (kc + 2 < 4) load_A(kc + 2, kc & 1);   // refill the buffer just drained
    }

    // ---------------- epilogue ----------------
    const int gid = lane >> 2, tid2 = lane & 3;

    if (mode == 0) {
        #pragma unroll
        for (int i = 0; i < 2; i++) {
            int m = m0 + wid * 16 + gid + i * 8;
            #pragma unroll
            for (int nb = 0; nb < 12; nb++) {
                int g = nb >> 2, cb = nb & 3;
                #pragma unroll
                for (int j = 0; j < 2; j++) {
                    int c = cb * 8 + tid2 * 2 + j;
                    g_Gx[(size_t)m * 768 + ct * 96 + g * 32 + c] =
                        acc[nb][i * 2 + j] + b_ih[g * 256 + ct * 32 + c];
                }
            }
        }
    } else {
        __half* __restrict__ Hdh = g_Hhi[dst];
        __half* __restrict__ Hdl = g_Hlo[dst];
        #pragma unroll
        for (int i = 0; i < 2; i++) {
            int m = m0 + wid * 16 + gid + i * 8;
            int l = m & 1023;
            bool valid = (l - (KW - 1) + t) >= 0;
            const float* gx = &g_Gx[(size_t)(m - (KW - 1) + t) * 768 + ct * 96];
            #pragma unroll
            for (int cb = 0; cb < 4; cb++) {
                #pragma unroll
                for (int j = 0; j < 2; j++) {
                    int c = cb * 8 + tid2 * 2 + j;
                    int col = ct * 32 + c;
                    float gir, giz, gin;
                    if (valid) { gir = gx[c]; giz = gx[32 + c]; gin = gx[64 + c]; }
                    else {
                        gir = b_ih[col];
                        giz = b_ih[256 + col];
                        gin = b_ih[512 + col];
                    }
                    float r = 1.f / (1.f + __expf(-(gir + acc[cb][i * 2 + j] +
                                                    b_hh[col])));
                    float z = 1.f / (1.f + __expf(-(giz + acc[4 + cb][i * 2 + j] +
                                                    b_hh[256 + col])));
                    float n = tanhf(fmaf(r, acc[8 + cb][i * 2 + j] +
                                            b_hh[512 + col], gin));
                    size_t ga = (size_t)m * 256 + col;
                    float hp = __half2float(Ahi[ga]) + __half2float(Alo[ga]);
                    float h = fmaf(z, hp - n, n);
                    if (t == KW - 1) {
                        fout[ga] = h;
                    } else {
                        __half hh = __float2half(h);
                        Hdh[ga] = hh;
                        Hdl[ga] = __float2half(h - __half2float(hh));
                    }
                }
            }
        }
    }
}

extern "C" void kernel_launch(void* const* d_in, const int* in_sizes, int n_in,
                              void* d_out, int out_size)
{
    const float* x    = (const float*)d_in[0];
    const float* W_ih = (const float*)d_in[1];
    const float* W_hh = (const float*)d_in[2];
    const float* b_ih = (const float*)d_in[3];
    const float* b_hh = (const float*)d_in[4];
    float* out = (float*)d_out;

    cudaFuncSetAttribute(gemm_fused,
                         cudaFuncAttributeMaxDynamicSharedMemorySize, SMEM_BYTES);

    pack_x_kernel<<<MM * 256 / 256, 256>>>(x);
    pack_w_kernel<<<8 * 4 * 96 * 64 / 256, 256>>>(W_ih, W_hh);

    gemm_fused<<<dim3(8, MM / 128), 256, SMEM_BYTES>>>(
        0, 0, 0, 0, b_ih, b_hh, nullptr);

    step0_kernel<<<MM, 256>>>(b_ih, b_hh);

    for (int t = 1; t < KW; t++) {
        gemm_fused<<<dim3(8, MM / 128), 256, SMEM_BYTES>>>(
            1, t, (t - 1) & 1, t & 1, b_ih, b_hh, (t == KW - 1) ? out : nullptr);
    }
}

// round 5
// speedup vs baseline: 1.1372x; 1.1372x over previous
#include <cuda_runtime.h>
#include <cuda_fp16.h>
#include <cstdint>
#include <math.h>

#define MM 16384          // B*L
#define KW 16             // window

// ---------------------------------------------------------------------------
// Device scratch (allocation-free rule: device globals)
// ---------------------------------------------------------------------------
__device__ __half g_xhi[(size_t)MM * 256];
__device__ __half g_xlo[(size_t)MM * 256];
__device__ __half g_Hhi[2][(size_t)MM * 256];
__device__ __half g_Hlo[2][(size_t)MM * 256];
__device__ float  g_Gx[(size_t)MM * 768];          // x@W_ih^T + b_ih, gate-major per ct
// Packed weights: [ct][kc][row96][k64], row = sub*48 + gate*16 + c16
__device__ __half g_Wih_p[8 * 4 * 96 * 64];
__device__ __half g_Whh_p[8 * 4 * 96 * 64];

#define SWZ(o) ((o) ^ (((o) >> 3) & 0x70))

// SMEM: B resident (4 chunks x 96 x 128B = 48KB), A double buffer (2 x 32KB)
#define OFF_B 0
#define OFF_A 49152
#define SMEM_BYTES 114688

// ---------------------------------------------------------------------------
// PTX helpers
// ---------------------------------------------------------------------------
__device__ __forceinline__ uint32_t smem_u32(const void* p) {
    uint32_t a;
    asm("{ .reg .u64 t; cvta.to.shared.u64 t, %1; cvt.u32.u64 %0, t; }"
        : "=r"(a) : "l"(p));
    return a;
}
__device__ __forceinline__ void cp16(uint32_t d, const void* s) {
    asm volatile("cp.async.cg.shared.global [%0], [%1], 16;"
                 :: "r"(d), "l"(s) : "memory");
}
__device__ __forceinline__ void cp_commit() { asm volatile("cp.async.commit_group;" ::: "memory"); }
__device__ __forceinline__ void cp_wait1()  { asm volatile("cp.async.wait_group 1;" ::: "memory"); }
__device__ __forceinline__ void cp_wait0()  { asm volatile("cp.async.wait_group 0;" ::: "memory"); }

__device__ __forceinline__ void ldm4(uint32_t a, uint32_t* r) {
    asm volatile("ldmatrix.sync.aligned.m8n8.x4.shared.b16 {%0,%1,%2,%3}, [%4];"
                 : "=r"(r[0]), "=r"(r[1]), "=r"(r[2]), "=r"(r[3]) : "r"(a));
}
__device__ __forceinline__ void mma16816(float* c, const uint32_t* a, const uint32_t* b) {
    asm volatile("mma.sync.aligned.m16n8k16.row.col.f32.f16.f16.f32 "
                 "{%0,%1,%2,%3}, {%4,%5,%6,%7}, {%8,%9}, {%0,%1,%2,%3};"
                 : "+f"(c[0]), "+f"(c[1]), "+f"(c[2]), "+f"(c[3])
                 : "r"(a[0]), "r"(a[1]), "r"(a[2]), "r"(a[3]), "r"(b[0]), "r"(b[1]));
}

// ---------------------------------------------------------------------------
// Prep kernels
// ---------------------------------------------------------------------------
__global__ void pack_x_kernel(const float* __restrict__ x) {
    size_t i = (size_t)blockIdx.x * 256 + threadIdx.x;
    float f = x[i];
    __half h = __float2half(f);
    g_xhi[i] = h;
    g_xlo[i] = __float2half(f - __half2float(h));
}

// row = sub*48 + g*16 + c  ->  W row = g*256 + ct*32 + sub*16 + c
__global__ void pack_w_kernel(const float* __restrict__ W_ih,
                              const float* __restrict__ W_hh) {
    int idx = blockIdx.x * 256 + threadIdx.x;        // < 196608
    int k   = idx & 63;
    int r2  = idx >> 6;
    int row = r2 % 96;
    int r3  = r2 / 96;
    int kc  = r3 & 3;
    int ct  = r3 >> 2;
    int sub = row / 48;
    int rem = row % 48;
    int g = rem >> 4, c = rem & 15;
    int widx = (g * 256 + ct * 32 + sub * 16 + c) * 256 + kc * 64 + k;
    g_Wih_p[idx] = __float2half(W_ih[widx]);
    g_Whh_p[idx] = __float2half(W_hh[widx]);
}

// ---------------------------------------------------------------------------
// Step 0 (h = 0): pure elementwise
// ---------------------------------------------------------------------------
__global__ void step0_kernel(const float* __restrict__ b_ih,
                             const float* __restrict__ b_hh) {
    int idx = blockIdx.x * 256 + threadIdx.x;
    int m = idx >> 8, col = idx & 255;
    int ct = col >> 5, c = col & 31;
    int l = m & 1023;
    float gir, giz, gin;
    if (l - (KW - 1) >= 0) {
        const float* gx = &g_Gx[(size_t)(m - (KW - 1)) * 768 + ct * 96];
        gir = gx[c]; giz = gx[32 + c]; gin = gx[64 + c];
    } else {
        gir = b_ih[col];
        giz = b_ih[256 + col];
        gin = b_ih[512 + col];
    }
    float r = 1.f / (1.f + __expf(-(gir + b_hh[col])));
    float z = 1.f / (1.f + __expf(-(giz + b_hh[256 + col])));
    float n = tanhf(fmaf(r, b_hh[512 + col], gin));
    float h = (1.f - z) * n;
    __half hh = __float2half(h);
    g_Hhi[0][idx] = hh;
    g_Hlo[0][idx] = __float2half(h - __half2float(hh));
}

// ---------------------------------------------------------------------------
// Fused GEMM (mma.sync fp16 -> fp32) + epilogue
//   mode 0: Gx = x @ W_ih^T + b_ih
//   mode 1: gh = h @ W_hh^T + GRU update
// CTA 128M x 96N, 8 warps as 4 M-groups x 2 N-subs; warp tile 32M x 48N.
// Warp N covers 16 h-cols x 3 gates (gate-interleaved packing), so the
// whole GRU update stays in-register. lo-plane A corrects n-gate only.
// ---------------------------------------------------------------------------
__global__ void __launch_bounds__(256, 2)
gemm_fused(int mode, int t, int src, int dst,
           const float* __restrict__ b_ih, const float* __restrict__ b_hh,
           float* __restrict__ fout)
{
    extern __shared__ char smem[];
    const int tid = threadIdx.x, wid = tid >> 5, lane = tid & 31;
    const int mg  = wid & 3;           // M group (32 rows)
    const int sub = wid >> 2;          // N sub (16 h-cols x 3 gates)
    const int ct  = blockIdx.x;
    const int m0  = blockIdx.y * 128;
    const uint32_t sb = smem_u32(smem);

    const __half* __restrict__ Ahi = (mode == 0) ? g_xhi : g_Hhi[src];
    const __half* __restrict__ Alo = (mode == 0) ? g_xlo : g_Hlo[src];
    const __half* __restrict__ B   = (mode == 0) ? g_Wih_p : g_Whh_p;

    float acc[2][6][4];
    #pragma unroll
    for (int mi = 0; mi < 2; mi++)
        #pragma unroll
        for (int p = 0; p < 6; p++)
            #pragma unroll
            for (int j = 0; j < 4; j++) acc[mi][p][j] = 0.f;

    // B: all 4 k-chunks, resident (part of cp.async group 0)
    {
        const __half* Bbase = B + (size_t)ct * 4 * 96 * 64;
        #pragma unroll
        for (int r = 0; r < 12; r++) {
            int idx = tid + 256 * r;             // < 3072
            int kc = idx / 768;
            int e  = idx - kc * 768;
            int row = e >> 3, u = e & 7;
            cp16(sb + OFF_B + kc * 12288 + SWZ(row * 128 + u * 16),
                 Bbase + (size_t)(kc * 96 + row) * 64 + u * 8);
        }
    }

    auto load_A = [&](int kc, int buf) {
        uint32_t base = sb + OFF_A + buf * 32768;
        #pragma unroll
        for (int r = 0; r < 4; r++) {
            int idx = tid + 256 * r;             // < 1024
            int row = idx >> 3, u = idx & 7;
            size_t off = (size_t)(m0 + row) * 256 + kc * 64 + u * 8;
            uint32_t d = SWZ(row * 128 + u * 16);
            cp16(base + d, Ahi + off);
            cp16(base + 16384 + d, Alo + off);
        }
        cp_commit();
    };

    load_A(0, 0);       // group 0 = B + A0

    #pragma unroll 1
    for (int kc = 0; kc < 4; kc++) {
        // prefetch next chunk BEFORE waiting: overlaps with this chunk's MMAs
        if (kc + 1 < 4) { load_A(kc + 1, (kc + 1) & 1); cp_wait1(); }
        else            { cp_wait0(); }
        __syncthreads();

        uint32_t abufh = sb + OFF_A + (kc & 1) * 32768;
        uint32_t abufl = abufh + 16384;
        uint32_t bbuf  = sb + OFF_B + kc * 12288;

        #pragma unroll
        for (int ks = 0; ks < 4; ks++) {
            uint32_t af[2][4], al[2][4];
            #pragma unroll
            for (int mi = 0; mi < 2; mi++) {
                int row = mg * 32 + mi * 16 + (lane & 15);
                int colb = ks * 32 + ((lane >> 4) << 4);
                uint32_t d = SWZ(row * 128 + colb);
                ldm4(abufh + d, af[mi]);
                ldm4(abufl + d, al[mi]);
            }
            #pragma unroll
            for (int q = 0; q < 3; q++) {        // q: gate (0=r,1=z,2=n)
                uint32_t bf[4];
                int n = sub * 48 + q * 16 + (lane & 7) + ((lane >> 4) << 3);
                int colb = ks * 32 + (((lane >> 3) & 1) << 4);
                ldm4(bbuf + SWZ(n * 128 + colb), bf);
                #pragma unroll
                for (int mi = 0; mi < 2; mi++) {
                    mma16816(acc[mi][2 * q + 0], af[mi], bf + 0);
                    mma16816(acc[mi][2 * q + 1], af[mi], bf + 2);
                    if (q == 2) {                // lo correction: n-gate only
                        mma16816(acc[mi][2 * q + 0], al[mi], bf + 0);
                        mma16816(acc[mi][2 * q + 1], al[mi], bf + 2);
                    }
                }
            }
        }
        __syncthreads();
    }

    // ---------------- epilogue (all in registers) ----------------
    const int gid = lane >> 2, tid2 = lane & 3;

    if (mode == 0) {
        #pragma unroll
        for (int mi = 0; mi < 2; mi++) {
            #pragma unroll
            for (int i = 0; i < 2; i++) {
                int m = m0 + mg * 32 + mi * 16 + gid + i * 8;
                #pragma unroll
                for (int q = 0; q < 3; q++) {
                    #pragma unroll
                    for (int cb = 0; cb < 2; cb++) {
                        #pragma unroll
                        for (int j = 0; j < 2; j++) {
                            int c = sub * 16 + cb * 8 + tid2 * 2 + j;  // h-col in 0..31
                            g_Gx[(size_t)m * 768 + ct * 96 + q * 32 + c] =
                                acc[mi][2 * q + cb][i * 2 + j] +
                                b_ih[q * 256 + ct * 32 + c];
                        }
                    }
                }
            }
        }
    } else {
        __half* __restrict__ Hdh = g_Hhi[dst];
        __half* __restrict__ Hdl = g_Hlo[dst];
        #pragma unroll
        for (int mi = 0; mi < 2; mi++) {
            #pragma unroll
            for (int i = 0; i < 2; i++) {
                int m = m0 + mg * 32 + mi * 16 + gid + i * 8;
                int l = m & 1023;
                bool valid = (l - (KW - 1) + t) >= 0;
                const float* gx = &g_Gx[(size_t)(m - (KW - 1) + t) * 768 + ct * 96];
                #pragma unroll
                for (int cb = 0; cb < 2; cb++) {
                    #pragma unroll
                    for (int j = 0; j < 2; j++) {
                        int c = sub * 16 + cb * 8 + tid2 * 2 + j;   // 0..31
                        int col = ct * 32 + c;
                        float gir, giz, gin;
                        if (valid) { gir = gx[c]; giz = gx[32 + c]; gin = gx[64 + c]; }
                        else {
                            gir = b_ih[col];
                            giz = b_ih[256 + col];
                            gin = b_ih[512 + col];
                        }
                        float rr = 1.f / (1.f + __expf(-(gir + acc[mi][0 + cb][i * 2 + j] +
                                                         b_hh[col])));
                        float zz = 1.f / (1.f + __expf(-(giz + acc[mi][2 + cb][i * 2 + j] +
                                                         b_hh[256 + col])));
                        float nn = tanhf(fmaf(rr, acc[mi][4 + cb][i * 2 + j] +
                                                  b_hh[512 + col], gin));
                        size_t ga = (size_t)m * 256 + col;
                        float hp = __half2float(Ahi[ga]) + __half2float(Alo[ga]);
                        float h = fmaf(zz, hp - nn, nn);   // (1-z)*n + z*hprev
                        if (t == KW - 1) {
                            fout[ga] = h;
                        } else {
                            __half hh = __float2half(h);
                            Hdh[ga] = hh;
                            Hdl[ga] = __float2half(h - __half2float(hh));
                        }
                    }
                }
            }
        }
    }
}

// ---------------------------------------------------------------------------
extern "C" void kernel_launch(void* const* d_in, const int* in_sizes, int n_in,
                              void* d_out, int out_size)
{
    const float* x    = (const float*)d_in[0];
    const float* W_ih = (const float*)d_in[1];
    const float* W_hh = (const float*)d_in[2];
    const float* b_ih = (const float*)d_in[3];
    const float* b_hh = (const float*)d_in[4];
    float* out = (float*)d_out;

    cudaFuncSetAttribute(gemm_fused,
                         cudaFuncAttributeMaxDynamicSharedMemorySize, SMEM_BYTES);

    pack_x_kernel<<<MM * 256 / 256, 256>>>(x);
    pack_w_kernel<<<8 * 4 * 96 * 64 / 256, 256>>>(W_ih, W_hh);

    // Gx = x @ W_ih^T + b_ih
    gemm_fused<<<dim3(8, MM / 128), 256, SMEM_BYTES>>>(
        0, 0, 0, 0, b_ih, b_hh, nullptr);

    // step 0 (h = 0): elementwise
    step0_kernel<<<MM, 256>>>(b_ih, b_hh);

    // steps 1..15: fused GEMM + GRU update; last writes d_out
    for (int t = 1; t < KW; t++) {
        gemm_fused<<<dim3(8, MM / 128), 256, SMEM_BYTES>>>(
            1, t, (t - 1) & 1, t & 1, b_ih, b_hh, (t == KW - 1) ? out : nullptr);
    }
}